// round 1
// baseline (speedup 1.0000x reference)
#include <cuda_runtime.h>
#include <cstdint>

#define FULL 0xffffffffu

static constexpr int S = 8;
static constexpr int N = 4096;
static constexpr int M = 64;
// L=20, R_CS=2, R_C=6

__device__ float g_v8[32];   // v8[tt][8] = td_table[tt] @ en1_w

// ---------------------------------------------------------------------------
// Precompute: collapse species-pair MLPs (es, fs) + en layer-1 weight product
// for the 4 possible (type_i, type_j) pairs.
// ---------------------------------------------------------------------------
__global__ void precompute_v8_kernel(
    const float* __restrict__ es1_w, const float* __restrict__ es1_b,
    const float* __restrict__ es2_w, const float* __restrict__ es2_b,
    const float* __restrict__ fs1_w, const float* __restrict__ fs1_b,
    const float* __restrict__ fs2_w, const float* __restrict__ fs2_b,
    const float* __restrict__ en1_w)
{
    int tt = threadIdx.x;
    if (tt >= 4) return;
    float ti = (float)(tt >> 1);
    float tj = (float)(tt & 1);

    float e[4];
    // forward pair (ti, tj)
    {
        float h[4];
        #pragma unroll
        for (int k = 0; k < 4; k++)
            h[k] = fmaxf(ti * es1_w[k] + tj * es1_w[4 + k] + es1_b[k], 0.f);
        #pragma unroll
        for (int k = 0; k < 4; k++) {
            float a = es2_b[k];
            #pragma unroll
            for (int j = 0; j < 4; j++) a += h[j] * es2_w[j * 4 + k];
            e[k] = a;
        }
    }
    // swapped pair (tj, ti)
    {
        float h[4];
        #pragma unroll
        for (int k = 0; k < 4; k++)
            h[k] = fmaxf(tj * es1_w[k] + ti * es1_w[4 + k] + es1_b[k], 0.f);
        #pragma unroll
        for (int k = 0; k < 4; k++) {
            float a = es2_b[k];
            #pragma unroll
            for (int j = 0; j < 4; j++) a += h[j] * es2_w[j * 4 + k];
            e[k] += a;
        }
    }
    // fs MLP: Linear -> relu -> Linear
    float y[4];
    #pragma unroll
    for (int k = 0; k < 4; k++) {
        float a = fs1_b[k];
        #pragma unroll
        for (int j = 0; j < 4; j++) a += e[j] * fs1_w[j * 4 + k];
        y[k] = fmaxf(a, 0.f);
    }
    float td[4];
    #pragma unroll
    for (int k = 0; k < 4; k++) {
        float a = fs2_b[k];
        #pragma unroll
        for (int j = 0; j < 4; j++) a += y[j] * fs2_w[j * 4 + k];
        td[k] = a;
    }
    // fold into en layer-1: v8[o] = sum_d td[d] * en1_w[d][o]
    #pragma unroll
    for (int o = 0; o < 8; o++) {
        float a = 0.f;
        #pragma unroll
        for (int d = 0; d < 4; d++) a += td[d] * en1_w[d * 8 + o];
        g_v8[tt * 8 + o] = a;
    }
}

// ---------------------------------------------------------------------------
// Main kernel: one warp per atom.
//   Phase 1 (lane = neighbor): geometry, smooth cutoff, r_tilde -> shared
//   Phase 2 (warp-cooperative, survivors only): G MLP, A[32][4] accumulation
//   Epilogue: D[g][k] = sum_d A[g][d]*A[k][d], write 32x16 per atom
// ---------------------------------------------------------------------------
__global__ __launch_bounds__(256, 4)
void descriptor_kernel(
    const float* __restrict__ pos,     // [S,N,3]
    const int*   __restrict__ types,   // [S,N]
    const int*   __restrict__ neigh,   // [S,N,M]
    const float* __restrict__ en1_b,   // [8]
    const float* __restrict__ en2_w,   // [8,16]
    const float* __restrict__ en2_b,   // [16]
    const float* __restrict__ en3_w,   // [16,32]
    const float* __restrict__ en3_b,   // [32]
    float*       __restrict__ out)     // [S,N,32,16]
{
    __shared__ float  sh_v8[32];
    __shared__ float4 sh_rt[8][32];

    const int tid  = threadIdx.x;
    const int lane = tid & 31;
    const int w    = tid >> 5;

    if (tid < 32) sh_v8[tid] = g_v8[tid];

    // register-resident weights: lane g owns en3 column g; lane owns en2 column (lane&15)
    const int g = lane;
    const int c = lane & 15;
    float W3[16], W2[8], b1r[8];
    #pragma unroll
    for (int j = 0; j < 16; j++) W3[j] = __ldg(&en3_w[j * 32 + g]);
    #pragma unroll
    for (int j = 0; j < 8; j++)  W2[j] = __ldg(&en2_w[j * 16 + c]);
    #pragma unroll
    for (int j = 0; j < 8; j++)  b1r[j] = __ldg(&en1_b[j]);
    const float b2c = __ldg(&en2_b[c]);
    const float b3g = __ldg(&en3_b[g]);
    __syncthreads();

    const int atom = blockIdx.x * 8 + w;      // atom = s*N + n
    const int s_idx = atom >> 12;             // N = 4096

    const float xi = pos[atom * 3 + 0];
    const float yi = pos[atom * 3 + 1];
    const float zi = pos[atom * 3 + 2];
    const int   ti = types[atom];

    float A0 = 0.f, A1 = 0.f, A2 = 0.f, A3 = 0.f;
    const int* nl = neigh + (size_t)atom * M;

    #pragma unroll
    for (int p = 0; p < 2; p++) {
        const int m  = p * 32 + lane;
        const int nb = nl[m];
        const int jj = (nb < 0) ? 0 : nb;
        const int bj = (s_idx << 12) + jj;

        const float px = pos[bj * 3 + 0];
        const float py = pos[bj * 3 + 1];
        const float pz = pos[bj * 3 + 2];

        float dx = px - xi; dx -= 20.f * rintf(dx * 0.05f);
        float dy = py - yi; dy -= 20.f * rintf(dy * 0.05f);
        float dz = pz - zi; dz -= 20.f * rintf(dz * 0.05f);

        const float r2 = fmaf(dx, dx, fmaf(dy, dy, fmaf(dz, dz, 1e-12f)));
        const float r  = sqrtf(r2);

        float sw;
        if (r < 2.f)      sw = 1.f;
        else if (r < 6.f) sw = fmaf(0.5f, cospif((r - 2.f) * 0.25f), 0.5f);
        else              sw = 0.f;

        const float rinv  = 1.f / r;
        const float s_ij  = (nb < 0) ? 0.f : sw * rinv;
        const float srinv = s_ij * rinv;

        __syncwarp();
        sh_rt[w][lane] = make_float4(s_ij, dx * srinv, dy * srinv, dz * srinv);
        const int ttl = ti * 2 + types[bj];
        __syncwarp();

        unsigned ball = __ballot_sync(FULL, s_ij != 0.f);
        while (ball) {
            const int mm = __ffs(ball) - 1;
            ball &= ball - 1;

            const float4 rtm = sh_rt[w][mm];
            const int    ttm = __shfl_sync(FULL, ttl, mm);
            const float  sm  = rtm.x;

            // layer 1+2: each lane computes h2 for column (lane&15)
            float h2 = b2c;
            #pragma unroll
            for (int j = 0; j < 8; j++) {
                const float h1 = fmaxf(fmaf(sm, sh_v8[ttm * 8 + j], b1r[j]), 0.f);
                h2 = fmaf(h1, W2[j], h2);
            }
            h2 = fmaxf(h2, 0.f);

            // layer 3: lane g computes G[g]
            float G = b3g;
            #pragma unroll
            for (int j = 0; j < 16; j++)
                G = fmaf(__shfl_sync(FULL, h2, j), W3[j], G);

            A0 = fmaf(G, rtm.x, A0);
            A1 = fmaf(G, rtm.y, A1);
            A2 = fmaf(G, rtm.z, A2);
            A3 = fmaf(G, rtm.w, A3);
        }
    }

    // D[g][k] = sum_d A[g][d] * A[k][d], k < 16
    float d[16];
    #pragma unroll
    for (int k = 0; k < 16; k++) {
        const float B0 = __shfl_sync(FULL, A0, k);
        const float B1 = __shfl_sync(FULL, A1, k);
        const float B2 = __shfl_sync(FULL, A2, k);
        const float B3 = __shfl_sync(FULL, A3, k);
        d[k] = fmaf(A0, B0, fmaf(A1, B1, fmaf(A2, B2, A3 * B3)));
    }

    float4* o4 = reinterpret_cast<float4*>(out + (size_t)atom * 512 + g * 16);
    o4[0] = make_float4(d[0],  d[1],  d[2],  d[3]);
    o4[1] = make_float4(d[4],  d[5],  d[6],  d[7]);
    o4[2] = make_float4(d[8],  d[9],  d[10], d[11]);
    o4[3] = make_float4(d[12], d[13], d[14], d[15]);
}

// ---------------------------------------------------------------------------
extern "C" void kernel_launch(void* const* d_in, const int* in_sizes, int n_in,
                              void* d_out, int out_size)
{
    const float* inputs      = (const float*)d_in[0];
    const int*   input_types = (const int*)  d_in[1];
    const int*   neigh_list  = (const int*)  d_in[2];
    const float* es1_w = (const float*)d_in[3];
    const float* es1_b = (const float*)d_in[4];
    const float* es2_w = (const float*)d_in[5];
    const float* es2_b = (const float*)d_in[6];
    const float* fs1_w = (const float*)d_in[7];
    const float* fs1_b = (const float*)d_in[8];
    const float* fs2_w = (const float*)d_in[9];
    const float* fs2_b = (const float*)d_in[10];
    const float* en1_w = (const float*)d_in[11];
    const float* en1_b = (const float*)d_in[12];
    const float* en2_w = (const float*)d_in[13];
    const float* en2_b = (const float*)d_in[14];
    const float* en3_w = (const float*)d_in[15];
    const float* en3_b = (const float*)d_in[16];
    float* out = (float*)d_out;

    precompute_v8_kernel<<<1, 4>>>(es1_w, es1_b, es2_w, es2_b,
                                   fs1_w, fs1_b, fs2_w, fs2_b, en1_w);

    const int atoms = S * N;                 // 32768
    descriptor_kernel<<<atoms / 8, 256>>>(inputs, input_types, neigh_list,
                                          en1_b, en2_w, en2_b, en3_w, en3_b,
                                          out);
}

// round 2
// speedup vs baseline: 1.0401x; 1.0401x over previous
#include <cuda_runtime.h>
#include <cstdint>

#define FULL 0xffffffffu

static constexpr int S = 8;
static constexpr int N = 4096;
static constexpr int M = 64;
// L=20, R_CS=2, R_C=6

__device__ float g_v8[32];   // v8[tt][8] = td_table[tt] @ en1_w

// ---------------------------------------------------------------------------
// Precompute: collapse species-pair MLPs (es, fs) + en layer-1 weight product
// ---------------------------------------------------------------------------
__global__ void precompute_v8_kernel(
    const float* __restrict__ es1_w, const float* __restrict__ es1_b,
    const float* __restrict__ es2_w, const float* __restrict__ es2_b,
    const float* __restrict__ fs1_w, const float* __restrict__ fs1_b,
    const float* __restrict__ fs2_w, const float* __restrict__ fs2_b,
    const float* __restrict__ en1_w)
{
    int tt = threadIdx.x;
    if (tt >= 4) return;
    float ti = (float)(tt >> 1);
    float tj = (float)(tt & 1);

    float e[4];
    {
        float h[4];
        #pragma unroll
        for (int k = 0; k < 4; k++)
            h[k] = fmaxf(ti * es1_w[k] + tj * es1_w[4 + k] + es1_b[k], 0.f);
        #pragma unroll
        for (int k = 0; k < 4; k++) {
            float a = es2_b[k];
            #pragma unroll
            for (int j = 0; j < 4; j++) a += h[j] * es2_w[j * 4 + k];
            e[k] = a;
        }
    }
    {
        float h[4];
        #pragma unroll
        for (int k = 0; k < 4; k++)
            h[k] = fmaxf(tj * es1_w[k] + ti * es1_w[4 + k] + es1_b[k], 0.f);
        #pragma unroll
        for (int k = 0; k < 4; k++) {
            float a = es2_b[k];
            #pragma unroll
            for (int j = 0; j < 4; j++) a += h[j] * es2_w[j * 4 + k];
            e[k] += a;
        }
    }
    float y[4];
    #pragma unroll
    for (int k = 0; k < 4; k++) {
        float a = fs1_b[k];
        #pragma unroll
        for (int j = 0; j < 4; j++) a += e[j] * fs1_w[j * 4 + k];
        y[k] = fmaxf(a, 0.f);
    }
    float td[4];
    #pragma unroll
    for (int k = 0; k < 4; k++) {
        float a = fs2_b[k];
        #pragma unroll
        for (int j = 0; j < 4; j++) a += y[j] * fs2_w[j * 4 + k];
        td[k] = a;
    }
    #pragma unroll
    for (int o = 0; o < 8; o++) {
        float a = 0.f;
        #pragma unroll
        for (int d = 0; d < 4; d++) a += td[d] * en1_w[d * 8 + o];
        g_v8[tt * 8 + o] = a;
    }
}

// ---------------------------------------------------------------------------
// Main kernel: one warp per atom, 2 survivors per serialized iteration.
// ---------------------------------------------------------------------------
__global__ __launch_bounds__(256, 4)
void descriptor_kernel(
    const float* __restrict__ pos,     // [S,N,3]
    const int*   __restrict__ types,   // [S,N]
    const int*   __restrict__ neigh,   // [S,N,M]
    const float* __restrict__ en1_b,   // [8]
    const float* __restrict__ en2_w,   // [8,16]
    const float* __restrict__ en2_b,   // [16]
    const float* __restrict__ en3_w,   // [16,32]
    const float* __restrict__ en3_b,   // [32]
    float*       __restrict__ out)     // [S,N,32,16]
{
    __shared__ float  sh_v8[32];
    __shared__ float4 sh_rt[8][64];
    __shared__ int    sh_tt[8][64];

    const int tid  = threadIdx.x;
    const int lane = tid & 31;
    const int w    = tid >> 5;

    if (tid < 32) sh_v8[tid] = g_v8[tid];

    // lane g owns en3 column g; lane owns en2 column (lane&15) for its half's survivor
    const int g = lane;
    const int c = lane & 15;
    float W3[16], W2[8], b1r[8];
    #pragma unroll
    for (int j = 0; j < 16; j++) W3[j] = __ldg(&en3_w[j * 32 + g]);
    #pragma unroll
    for (int j = 0; j < 8; j++)  W2[j] = __ldg(&en2_w[j * 16 + c]);
    #pragma unroll
    for (int j = 0; j < 8; j++)  b1r[j] = __ldg(&en1_b[j]);
    const float b2c = __ldg(&en2_b[c]);
    const float b3g = __ldg(&en3_b[g]);
    __syncthreads();

    const int atom  = blockIdx.x * 8 + w;     // atom = s*N + n
    const int s_idx = atom >> 12;             // N = 4096

    const float xi = pos[atom * 3 + 0];
    const float yi = pos[atom * 3 + 1];
    const float zi = pos[atom * 3 + 2];
    const int   ti = types[atom];

    const int* nl = neigh + (size_t)atom * M;

    // -------- Phase 1: geometry for 64 neighbors (2 per lane) --------
    unsigned b01[2];
    #pragma unroll
    for (int p = 0; p < 2; p++) {
        const int m  = p * 32 + lane;
        const int nb = nl[m];
        const int jj = (nb < 0) ? 0 : nb;
        const int bj = (s_idx << 12) + jj;

        const float px = pos[bj * 3 + 0];
        const float py = pos[bj * 3 + 1];
        const float pz = pos[bj * 3 + 2];

        float dx = px - xi; dx -= 20.f * rintf(dx * 0.05f);
        float dy = py - yi; dy -= 20.f * rintf(dy * 0.05f);
        float dz = pz - zi; dz -= 20.f * rintf(dz * 0.05f);

        const float r2   = fmaf(dx, dx, fmaf(dy, dy, fmaf(dz, dz, 1e-12f)));
        const float rinv = rsqrtf(r2);
        const float r    = r2 * rinv;

        float sw;
        if (r < 2.f)      sw = 1.f;
        else if (r < 6.f) sw = fmaf(0.5f, cospif((r - 2.f) * 0.25f), 0.5f);
        else              sw = 0.f;

        const float s_ij  = (nb < 0) ? 0.f : sw * rinv;
        const float srinv = s_ij * rinv;

        sh_rt[w][m] = make_float4(s_ij, dx * srinv, dy * srinv, dz * srinv);
        sh_tt[w][m] = ti * 2 + types[bj];
        b01[p] = __ballot_sync(FULL, s_ij != 0.f);
    }
    __syncwarp();

    uint64_t mask = (uint64_t)b01[0] | ((uint64_t)b01[1] << 32);

    float A0 = 0.f, A1 = 0.f, A2 = 0.f, A3 = 0.f;
    const bool hi = lane >= 16;

    // -------- Phase 2: warp-cooperative MLP, 2 survivors / iteration --------
    while (mask) {
        const int m1 = __ffsll((long long)mask) - 1;
        mask &= mask - 1;
        int m2 = -1;
        if (mask) { m2 = __ffsll((long long)mask) - 1; mask &= mask - 1; }

        const float4 rtA = sh_rt[w][m1];
        const float4 rtB = (m2 >= 0) ? sh_rt[w][m2] : make_float4(0.f, 0.f, 0.f, 0.f);
        const int    ttA = sh_tt[w][m1];
        const int    ttB = (m2 >= 0) ? sh_tt[w][m2] : 0;

        const float sm  = hi ? rtB.x : rtA.x;
        const int   ttm = hi ? ttB : ttA;
        const float* v8 = &sh_v8[ttm * 8];

        // layers 1+2: lanes 0-15 -> h2 columns of survivor A, lanes 16-31 -> B
        float h2 = b2c;
        #pragma unroll
        for (int j = 0; j < 8; j++) {
            const float h1 = fmaxf(fmaf(sm, v8[j], b1r[j]), 0.f);
            h2 = fmaf(h1, W2[j], h2);
        }
        h2 = fmaxf(h2, 0.f);

        // layer 3: lane g computes G[g] for both survivors (independent chains)
        float GA = b3g, GB = b3g;
        #pragma unroll
        for (int j = 0; j < 16; j++) {
            GA = fmaf(__shfl_sync(FULL, h2, j),      W3[j], GA);
            GB = fmaf(__shfl_sync(FULL, h2, j + 16), W3[j], GB);
        }

        A0 = fmaf(GA, rtA.x, fmaf(GB, rtB.x, A0));
        A1 = fmaf(GA, rtA.y, fmaf(GB, rtB.y, A1));
        A2 = fmaf(GA, rtA.z, fmaf(GB, rtB.z, A2));
        A3 = fmaf(GA, rtA.w, fmaf(GB, rtB.w, A3));
    }

    // -------- Epilogue: D[g][k] = sum_d A[g][d]*A[k][d], k < 16 --------
    float d[16];
    #pragma unroll
    for (int k = 0; k < 16; k++) {
        const float B0 = __shfl_sync(FULL, A0, k);
        const float B1 = __shfl_sync(FULL, A1, k);
        const float B2 = __shfl_sync(FULL, A2, k);
        const float B3 = __shfl_sync(FULL, A3, k);
        d[k] = fmaf(A0, B0, fmaf(A1, B1, fmaf(A2, B2, A3 * B3)));
    }

    float4* o4 = reinterpret_cast<float4*>(out + (size_t)atom * 512 + g * 16);
    o4[0] = make_float4(d[0],  d[1],  d[2],  d[3]);
    o4[1] = make_float4(d[4],  d[5],  d[6],  d[7]);
    o4[2] = make_float4(d[8],  d[9],  d[10], d[11]);
    o4[3] = make_float4(d[12], d[13], d[14], d[15]);
}

// ---------------------------------------------------------------------------
extern "C" void kernel_launch(void* const* d_in, const int* in_sizes, int n_in,
                              void* d_out, int out_size)
{
    const float* inputs      = (const float*)d_in[0];
    const int*   input_types = (const int*)  d_in[1];
    const int*   neigh_list  = (const int*)  d_in[2];
    const float* es1_w = (const float*)d_in[3];
    const float* es1_b = (const float*)d_in[4];
    const float* es2_w = (const float*)d_in[5];
    const float* es2_b = (const float*)d_in[6];
    const float* fs1_w = (const float*)d_in[7];
    const float* fs1_b = (const float*)d_in[8];
    const float* fs2_w = (const float*)d_in[9];
    const float* fs2_b = (const float*)d_in[10];
    const float* en1_w = (const float*)d_in[11];
    const float* en1_b = (const float*)d_in[12];
    const float* en2_w = (const float*)d_in[13];
    const float* en2_b = (const float*)d_in[14];
    const float* en3_w = (const float*)d_in[15];
    const float* en3_b = (const float*)d_in[16];
    float* out = (float*)d_out;

    precompute_v8_kernel<<<1, 4>>>(es1_w, es1_b, es2_w, es2_b,
                                   fs1_w, fs1_b, fs2_w, fs2_b, en1_w);

    const int atoms = S * N;                 // 32768
    descriptor_kernel<<<atoms / 8, 256>>>(inputs, input_types, neigh_list,
                                          en1_b, en2_w, en2_b, en3_w, en3_b,
                                          out);
}

// round 3
// speedup vs baseline: 1.2188x; 1.1718x over previous
#include <cuda_runtime.h>
#include <cstdint>

#define FULL 0xffffffffu

static constexpr int S = 8;
static constexpr int N = 4096;
static constexpr int M = 64;
static constexpr int SN = S * N;

__device__ float  g_v8[32];      // v8[tt][8] = td_table[tt] @ en1_w
__device__ float4 g_pos4[SN];    // (x, y, z, type)

// ---------------------------------------------------------------------------
// Prepass: pack positions+type into float4, and (block 0) collapse species
// MLPs into the 4-entry v8 table.
// ---------------------------------------------------------------------------
__global__ void pack_kernel(
    const float* __restrict__ pos, const int* __restrict__ types,
    const float* __restrict__ es1_w, const float* __restrict__ es1_b,
    const float* __restrict__ es2_w, const float* __restrict__ es2_b,
    const float* __restrict__ fs1_w, const float* __restrict__ fs1_b,
    const float* __restrict__ fs2_w, const float* __restrict__ fs2_b,
    const float* __restrict__ en1_w)
{
    const int i = blockIdx.x * blockDim.x + threadIdx.x;
    if (i < SN)
        g_pos4[i] = make_float4(pos[3 * i], pos[3 * i + 1], pos[3 * i + 2],
                                (float)types[i]);

    if (blockIdx.x == 0 && threadIdx.x < 4) {
        const int tt = threadIdx.x;
        const float ti = (float)(tt >> 1);
        const float tj = (float)(tt & 1);

        float e[4];
        {
            float h[4];
            #pragma unroll
            for (int k = 0; k < 4; k++)
                h[k] = fmaxf(ti * es1_w[k] + tj * es1_w[4 + k] + es1_b[k], 0.f);
            #pragma unroll
            for (int k = 0; k < 4; k++) {
                float a = es2_b[k];
                #pragma unroll
                for (int j = 0; j < 4; j++) a += h[j] * es2_w[j * 4 + k];
                e[k] = a;
            }
        }
        {
            float h[4];
            #pragma unroll
            for (int k = 0; k < 4; k++)
                h[k] = fmaxf(tj * es1_w[k] + ti * es1_w[4 + k] + es1_b[k], 0.f);
            #pragma unroll
            for (int k = 0; k < 4; k++) {
                float a = es2_b[k];
                #pragma unroll
                for (int j = 0; j < 4; j++) a += h[j] * es2_w[j * 4 + k];
                e[k] += a;
            }
        }
        float y[4];
        #pragma unroll
        for (int k = 0; k < 4; k++) {
            float a = fs1_b[k];
            #pragma unroll
            for (int j = 0; j < 4; j++) a += e[j] * fs1_w[j * 4 + k];
            y[k] = fmaxf(a, 0.f);
        }
        float td[4];
        #pragma unroll
        for (int k = 0; k < 4; k++) {
            float a = fs2_b[k];
            #pragma unroll
            for (int j = 0; j < 4; j++) a += y[j] * fs2_w[j * 4 + k];
            td[k] = a;
        }
        #pragma unroll
        for (int o = 0; o < 8; o++) {
            float a = 0.f;
            #pragma unroll
            for (int d = 0; d < 4; d++) a += td[d] * en1_w[d * 8 + o];
            g_v8[tt * 8 + o] = a;
        }
    }
}

// ---------------------------------------------------------------------------
// Main kernel: one warp per atom; LDS.128-broadcast cooperative MLP.
// ---------------------------------------------------------------------------
__global__ __launch_bounds__(256, 3)
void descriptor_kernel(
    const int*   __restrict__ neigh,   // [S,N,M]
    const float* __restrict__ en1_b,   // [8]
    const float* __restrict__ en2_w,   // [8,16]
    const float* __restrict__ en2_b,   // [16]
    const float* __restrict__ en3_w,   // [16,32]
    const float* __restrict__ en3_b,   // [32]
    float*       __restrict__ out)     // [S,N,32,16]
{
    __shared__ float4 sh_v8q[8];           // [tt*2 + half]
    __shared__ float4 sh_rt[8][64];
    __shared__ float  sh_h2[8][2][32];     // double-buffered

    const int tid  = threadIdx.x;
    const int lane = tid & 31;
    const int w    = tid >> 5;

    if (tid < 32) ((float*)sh_v8q)[tid] = g_v8[tid];

    // lane g owns en3 column g; lane owns en2 column (lane&15) for its half
    const int g = lane;
    const int c = lane & 15;
    float W3[16], W2[8], b1r[8];
    #pragma unroll
    for (int j = 0; j < 16; j++) W3[j] = __ldg(&en3_w[j * 32 + g]);
    #pragma unroll
    for (int j = 0; j < 8; j++)  W2[j] = __ldg(&en2_w[j * 16 + c]);
    #pragma unroll
    for (int j = 0; j < 8; j++)  b1r[j] = __ldg(&en1_b[j]);
    const float b2c = __ldg(&en2_b[c]);
    const float b3g = __ldg(&en3_b[g]);
    __syncthreads();

    const int atom  = blockIdx.x * 8 + w;     // atom = s*N + n
    const int s_idx = atom >> 12;             // N = 4096

    const float4 pi = g_pos4[atom];
    const int    ti = (int)pi.w;

    const int* nl = neigh + (size_t)atom * M;

    // -------- Phase 1: geometry for 64 neighbors (2 per lane) --------
    uint64_t mask = 0, t0m = 0, t1m = 0;
    #pragma unroll
    for (int p = 0; p < 2; p++) {
        const int m  = p * 32 + lane;
        const int nb = nl[m];
        const int jj = (nb < 0) ? 0 : nb;
        const int bj = (s_idx << 12) + jj;

        const float4 pj = g_pos4[bj];

        float dx = pj.x - pi.x; dx -= 20.f * rintf(dx * 0.05f);
        float dy = pj.y - pi.y; dy -= 20.f * rintf(dy * 0.05f);
        float dz = pj.z - pi.z; dz -= 20.f * rintf(dz * 0.05f);

        const float r2   = fmaf(dx, dx, fmaf(dy, dy, fmaf(dz, dz, 1e-12f)));
        const float rinv = rsqrtf(r2);
        const float r    = r2 * rinv;

        float sw;
        if (r < 2.f)      sw = 1.f;
        else if (r < 6.f) sw = fmaf(0.5f, cospif((r - 2.f) * 0.25f), 0.5f);
        else              sw = 0.f;

        const float s_ij  = (nb < 0) ? 0.f : sw * rinv;
        const float srinv = s_ij * rinv;

        sh_rt[w][m] = make_float4(s_ij, dx * srinv, dy * srinv, dz * srinv);
        const int tt = ti * 2 + (int)pj.w;

        const unsigned bb = __ballot_sync(FULL, s_ij != 0.f);
        const unsigned q0 = __ballot_sync(FULL, (tt & 1) != 0);
        const unsigned q1 = __ballot_sync(FULL, (tt & 2) != 0);
        mask |= (uint64_t)bb << (32 * p);
        t0m  |= (uint64_t)q0 << (32 * p);
        t1m  |= (uint64_t)q1 << (32 * p);
    }
    __syncwarp();

    float A0 = 0.f, A1 = 0.f, A2 = 0.f, A3 = 0.f;
    const bool hi = lane >= 16;
    int par = 0;

    // -------- Phase 2: 2 survivors / iteration, LDS-broadcast MLP --------
    while (mask) {
        const int m1 = __ffsll((long long)mask) - 1;
        mask &= mask - 1;
        int m2 = -1;
        if (mask) { m2 = __ffsll((long long)mask) - 1; mask &= mask - 1; }

        const float4 rtA = sh_rt[w][m1];
        const float4 rtB = (m2 >= 0) ? sh_rt[w][m2] : make_float4(0.f, 0.f, 0.f, 0.f);
        const int ttA = (int)((t0m >> m1) & 1) | ((int)((t1m >> m1) & 1) << 1);
        const int ttB = (m2 >= 0)
                      ? ((int)((t0m >> m2) & 1) | ((int)((t1m >> m2) & 1) << 1))
                      : 0;

        const float sm  = hi ? rtB.x : rtA.x;
        const int   ttm = hi ? ttB : ttA;
        const float4 v8lo = sh_v8q[ttm * 2 + 0];
        const float4 v8hi = sh_v8q[ttm * 2 + 1];

        // layers 1+2: lanes 0-15 -> survivor A columns, 16-31 -> survivor B
        float h2 = b2c;
        h2 = fmaf(fmaxf(fmaf(sm, v8lo.x, b1r[0]), 0.f), W2[0], h2);
        h2 = fmaf(fmaxf(fmaf(sm, v8lo.y, b1r[1]), 0.f), W2[1], h2);
        h2 = fmaf(fmaxf(fmaf(sm, v8lo.z, b1r[2]), 0.f), W2[2], h2);
        h2 = fmaf(fmaxf(fmaf(sm, v8lo.w, b1r[3]), 0.f), W2[3], h2);
        h2 = fmaf(fmaxf(fmaf(sm, v8hi.x, b1r[4]), 0.f), W2[4], h2);
        h2 = fmaf(fmaxf(fmaf(sm, v8hi.y, b1r[5]), 0.f), W2[5], h2);
        h2 = fmaf(fmaxf(fmaf(sm, v8hi.z, b1r[6]), 0.f), W2[6], h2);
        h2 = fmaf(fmaxf(fmaf(sm, v8hi.w, b1r[7]), 0.f), W2[7], h2);
        h2 = fmaxf(h2, 0.f);

        sh_h2[w][par][lane] = h2;
        __syncwarp();
        const float4* hh = reinterpret_cast<const float4*>(sh_h2[w][par]);

        // layer 3: lane g computes G[g] for both survivors (LDS.128 broadcast)
        float GA = b3g, GB = b3g;
        #pragma unroll
        for (int q = 0; q < 4; q++) {
            const float4 ha = hh[q];
            GA = fmaf(ha.x, W3[4 * q + 0], GA);
            GA = fmaf(ha.y, W3[4 * q + 1], GA);
            GA = fmaf(ha.z, W3[4 * q + 2], GA);
            GA = fmaf(ha.w, W3[4 * q + 3], GA);
        }
        #pragma unroll
        for (int q = 0; q < 4; q++) {
            const float4 hb = hh[4 + q];
            GB = fmaf(hb.x, W3[4 * q + 0], GB);
            GB = fmaf(hb.y, W3[4 * q + 1], GB);
            GB = fmaf(hb.z, W3[4 * q + 2], GB);
            GB = fmaf(hb.w, W3[4 * q + 3], GB);
        }
        par ^= 1;

        A0 = fmaf(GA, rtA.x, fmaf(GB, rtB.x, A0));
        A1 = fmaf(GA, rtA.y, fmaf(GB, rtB.y, A1));
        A2 = fmaf(GA, rtA.z, fmaf(GB, rtB.z, A2));
        A3 = fmaf(GA, rtA.w, fmaf(GB, rtB.w, A3));
    }

    // -------- Epilogue: D[g][k] = sum_d A[g][d]*A[k][d], k < 16 --------
    __syncwarp();
    sh_rt[w][lane] = make_float4(A0, A1, A2, A3);
    __syncwarp();

    float d[16];
    #pragma unroll
    for (int k = 0; k < 16; k++) {
        const float4 B = sh_rt[w][k];
        d[k] = fmaf(A0, B.x, fmaf(A1, B.y, fmaf(A2, B.z, A3 * B.w)));
    }

    float4* o4 = reinterpret_cast<float4*>(out + (size_t)atom * 512 + g * 16);
    o4[0] = make_float4(d[0],  d[1],  d[2],  d[3]);
    o4[1] = make_float4(d[4],  d[5],  d[6],  d[7]);
    o4[2] = make_float4(d[8],  d[9],  d[10], d[11]);
    o4[3] = make_float4(d[12], d[13], d[14], d[15]);
}

// ---------------------------------------------------------------------------
extern "C" void kernel_launch(void* const* d_in, const int* in_sizes, int n_in,
                              void* d_out, int out_size)
{
    const float* inputs      = (const float*)d_in[0];
    const int*   input_types = (const int*)  d_in[1];
    const int*   neigh_list  = (const int*)  d_in[2];
    const float* es1_w = (const float*)d_in[3];
    const float* es1_b = (const float*)d_in[4];
    const float* es2_w = (const float*)d_in[5];
    const float* es2_b = (const float*)d_in[6];
    const float* fs1_w = (const float*)d_in[7];
    const float* fs1_b = (const float*)d_in[8];
    const float* fs2_w = (const float*)d_in[9];
    const float* fs2_b = (const float*)d_in[10];
    const float* en1_w = (const float*)d_in[11];
    const float* en1_b = (const float*)d_in[12];
    const float* en2_w = (const float*)d_in[13];
    const float* en2_b = (const float*)d_in[14];
    const float* en3_w = (const float*)d_in[15];
    const float* en3_b = (const float*)d_in[16];
    float* out = (float*)d_out;

    pack_kernel<<<(SN + 255) / 256, 256>>>(inputs, input_types,
                                           es1_w, es1_b, es2_w, es2_b,
                                           fs1_w, fs1_b, fs2_w, fs2_b, en1_w);

    descriptor_kernel<<<SN / 8, 256>>>(neigh_list,
                                       en1_b, en2_w, en2_b, en3_w, en3_b,
                                       out);
}

// round 4
// speedup vs baseline: 1.2349x; 1.0132x over previous
#include <cuda_runtime.h>
#include <cstdint>

#define FULL 0xffffffffu

static constexpr int S = 8;
static constexpr int N = 4096;
static constexpr int M = 64;
static constexpr int SN = S * N;

__device__ float  g_v8[32];      // v8[tt][8] = td_table[tt] @ en1_w
__device__ float4 g_pos4[SN];    // (x, y, z, type)

// ---------------------------------------------------------------------------
// Prepass: pack positions+type into float4; block 0 collapses species MLPs.
// ---------------------------------------------------------------------------
__global__ void pack_kernel(
    const float* __restrict__ pos, const int* __restrict__ types,
    const float* __restrict__ es1_w, const float* __restrict__ es1_b,
    const float* __restrict__ es2_w, const float* __restrict__ es2_b,
    const float* __restrict__ fs1_w, const float* __restrict__ fs1_b,
    const float* __restrict__ fs2_w, const float* __restrict__ fs2_b,
    const float* __restrict__ en1_w)
{
    const int i = blockIdx.x * blockDim.x + threadIdx.x;
    if (i < SN)
        g_pos4[i] = make_float4(pos[3 * i], pos[3 * i + 1], pos[3 * i + 2],
                                (float)types[i]);

    if (blockIdx.x == 0 && threadIdx.x < 4) {
        const int tt = threadIdx.x;
        const float ti = (float)(tt >> 1);
        const float tj = (float)(tt & 1);

        float e[4];
        {
            float h[4];
            #pragma unroll
            for (int k = 0; k < 4; k++)
                h[k] = fmaxf(ti * es1_w[k] + tj * es1_w[4 + k] + es1_b[k], 0.f);
            #pragma unroll
            for (int k = 0; k < 4; k++) {
                float a = es2_b[k];
                #pragma unroll
                for (int j = 0; j < 4; j++) a += h[j] * es2_w[j * 4 + k];
                e[k] = a;
            }
        }
        {
            float h[4];
            #pragma unroll
            for (int k = 0; k < 4; k++)
                h[k] = fmaxf(tj * es1_w[k] + ti * es1_w[4 + k] + es1_b[k], 0.f);
            #pragma unroll
            for (int k = 0; k < 4; k++) {
                float a = es2_b[k];
                #pragma unroll
                for (int j = 0; j < 4; j++) a += h[j] * es2_w[j * 4 + k];
                e[k] += a;
            }
        }
        float y[4];
        #pragma unroll
        for (int k = 0; k < 4; k++) {
            float a = fs1_b[k];
            #pragma unroll
            for (int j = 0; j < 4; j++) a += e[j] * fs1_w[j * 4 + k];
            y[k] = fmaxf(a, 0.f);
        }
        float td[4];
        #pragma unroll
        for (int k = 0; k < 4; k++) {
            float a = fs2_b[k];
            #pragma unroll
            for (int j = 0; j < 4; j++) a += y[j] * fs2_w[j * 4 + k];
            td[k] = a;
        }
        #pragma unroll
        for (int o = 0; o < 8; o++) {
            float a = 0.f;
            #pragma unroll
            for (int d = 0; d < 4; d++) a += td[d] * en1_w[d * 8 + o];
            g_v8[tt * 8 + o] = a;
        }
    }
}

// ---------------------------------------------------------------------------
// Main kernel: one warp per atom; compacted survivors; 4 survivors/iteration.
// ---------------------------------------------------------------------------
__global__ __launch_bounds__(256)
void descriptor_kernel(
    const int*   __restrict__ neigh,   // [S,N,M]
    const float* __restrict__ en1_b,   // [8]
    const float* __restrict__ en2_w,   // [8,16]
    const float* __restrict__ en2_b,   // [16]
    const float* __restrict__ en3_w,   // [16,32]
    const float* __restrict__ en3_b,   // [32]
    float*       __restrict__ out)     // [S,N,32,16]
{
    __shared__ float4 sh_v8q[8];            // [tt*2 + half]
    __shared__ float4 sh_rt[8][68];         // compacted survivors (+pad)
    __shared__ int    sh_tt[8][68];
    __shared__ float  sh_h2[8][2][4][16];   // [warp][parity][survivor][col]

    const int tid  = threadIdx.x;
    const int lane = tid & 31;
    const int w    = tid >> 5;

    if (tid < 32) ((float*)sh_v8q)[tid] = g_v8[tid];

    // lane g owns en3 column g; lane owns en2 columns c0, c0+1 of its quarter
    const int g  = lane;
    const int c0 = (lane & 7) * 2;
    float  W3[16], b1r[8];
    float2 W2[8];
    #pragma unroll
    for (int j = 0; j < 16; j++) W3[j] = __ldg(&en3_w[j * 32 + g]);
    #pragma unroll
    for (int j = 0; j < 8; j++)
        W2[j] = *reinterpret_cast<const float2*>(&en2_w[j * 16 + c0]);
    #pragma unroll
    for (int j = 0; j < 8; j++)  b1r[j] = __ldg(&en1_b[j]);
    const float2 b2 = *reinterpret_cast<const float2*>(&en2_b[c0]);
    const float  b3g = __ldg(&en3_b[g]);
    __syncthreads();

    const int atom  = blockIdx.x * 8 + w;     // atom = s*N + n
    const int s_idx = atom >> 12;             // N = 4096

    const float4 pi = g_pos4[atom];
    const int    ti2 = 2 * (int)pi.w;

    // -------- Phase 1: geometry + ballot-popc compaction --------
    const int2 nb2 = reinterpret_cast<const int2*>(neigh + (size_t)atom * M)[lane];
    int cnt = 0;
    #pragma unroll
    for (int p = 0; p < 2; p++) {
        const int nb = (p == 0) ? nb2.x : nb2.y;
        const int jj = (nb < 0) ? 0 : nb;
        const int bj = (s_idx << 12) + jj;

        const float4 pj = g_pos4[bj];

        float dx = pj.x - pi.x; dx -= 20.f * rintf(dx * 0.05f);
        float dy = pj.y - pi.y; dy -= 20.f * rintf(dy * 0.05f);
        float dz = pj.z - pi.z; dz -= 20.f * rintf(dz * 0.05f);

        const float r2   = fmaf(dx, dx, fmaf(dy, dy, fmaf(dz, dz, 1e-12f)));
        const float rinv = rsqrtf(r2);
        const float r    = r2 * rinv;

        float sw;
        if (r < 2.f)      sw = 1.f;
        else if (r < 6.f) sw = fmaf(0.5f, cospif((r - 2.f) * 0.25f), 0.5f);
        else              sw = 0.f;

        const float s_ij  = (nb < 0) ? 0.f : sw * rinv;
        const float srinv = s_ij * rinv;

        const bool alive = (s_ij != 0.f);
        const unsigned bb = __ballot_sync(FULL, alive);
        if (alive) {
            const int pos = cnt + __popc(bb & ((1u << lane) - 1u));
            sh_rt[w][pos] = make_float4(s_ij, dx * srinv, dy * srinv, dz * srinv);
            sh_tt[w][pos] = ti2 + (int)pj.w;
        }
        cnt += __popc(bb);
    }
    // zero-pad 3 slots so 4-wide iterations are safe
    if (lane < 3) {
        sh_rt[w][cnt + lane] = make_float4(0.f, 0.f, 0.f, 0.f);
        sh_tt[w][cnt + lane] = 0;
    }
    __syncwarp();

    float A0 = 0.f, A1 = 0.f, A2 = 0.f, A3 = 0.f;
    const int qs = lane >> 3;    // which of 4 survivors this lane serves
    int par = 0;

    // -------- Phase 2: 4 survivors per iteration --------
    for (int i = 0; i < cnt; i += 4) {
        const float4 rt = sh_rt[w][i + qs];
        const int    tt = sh_tt[w][i + qs];
        const float4 v8lo = sh_v8q[tt * 2 + 0];
        const float4 v8hi = sh_v8q[tt * 2 + 1];
        const float  sm   = rt.x;

        // layers 1+2: two h2 columns (c0, c0+1) for this quarter's survivor
        float h1[8];
        h1[0] = fmaxf(fmaf(sm, v8lo.x, b1r[0]), 0.f);
        h1[1] = fmaxf(fmaf(sm, v8lo.y, b1r[1]), 0.f);
        h1[2] = fmaxf(fmaf(sm, v8lo.z, b1r[2]), 0.f);
        h1[3] = fmaxf(fmaf(sm, v8lo.w, b1r[3]), 0.f);
        h1[4] = fmaxf(fmaf(sm, v8hi.x, b1r[4]), 0.f);
        h1[5] = fmaxf(fmaf(sm, v8hi.y, b1r[5]), 0.f);
        h1[6] = fmaxf(fmaf(sm, v8hi.z, b1r[6]), 0.f);
        h1[7] = fmaxf(fmaf(sm, v8hi.w, b1r[7]), 0.f);

        float ha = b2.x, hb = b2.y;
        #pragma unroll
        for (int j = 0; j < 8; j++) {
            ha = fmaf(h1[j], W2[j].x, ha);
            hb = fmaf(h1[j], W2[j].y, hb);
        }
        ha = fmaxf(ha, 0.f);
        hb = fmaxf(hb, 0.f);

        *reinterpret_cast<float2*>(&sh_h2[w][par][qs][c0]) = make_float2(ha, hb);
        __syncwarp();

        // layer 3 + A accumulation for all 4 survivors (uniform broadcasts)
        const float (*hh)[16] = sh_h2[w][par];
        #pragma unroll
        for (int sv = 0; sv < 4; sv++) {
            const float4* hq = reinterpret_cast<const float4*>(hh[sv]);
            float G = b3g;
            #pragma unroll
            for (int q = 0; q < 4; q++) {
                const float4 hv = hq[q];
                G = fmaf(hv.x, W3[4 * q + 0], G);
                G = fmaf(hv.y, W3[4 * q + 1], G);
                G = fmaf(hv.z, W3[4 * q + 2], G);
                G = fmaf(hv.w, W3[4 * q + 3], G);
            }
            const float4 rs = sh_rt[w][i + sv];
            A0 = fmaf(G, rs.x, A0);
            A1 = fmaf(G, rs.y, A1);
            A2 = fmaf(G, rs.z, A2);
            A3 = fmaf(G, rs.w, A3);
        }
        par ^= 1;
    }

    // -------- Epilogue: D[g][k] = sum_d A[g][d]*A[k][d], k < 16 --------
    __syncwarp();
    sh_rt[w][lane] = make_float4(A0, A1, A2, A3);
    __syncwarp();

    float d[16];
    #pragma unroll
    for (int k = 0; k < 16; k++) {
        const float4 B = sh_rt[w][k];
        d[k] = fmaf(A0, B.x, fmaf(A1, B.y, fmaf(A2, B.z, A3 * B.w)));
    }

    float4* o4 = reinterpret_cast<float4*>(out + (size_t)atom * 512 + g * 16);
    o4[0] = make_float4(d[0],  d[1],  d[2],  d[3]);
    o4[1] = make_float4(d[4],  d[5],  d[6],  d[7]);
    o4[2] = make_float4(d[8],  d[9],  d[10], d[11]);
    o4[3] = make_float4(d[12], d[13], d[14], d[15]);
}

// ---------------------------------------------------------------------------
extern "C" void kernel_launch(void* const* d_in, const int* in_sizes, int n_in,
                              void* d_out, int out_size)
{
    const float* inputs      = (const float*)d_in[0];
    const int*   input_types = (const int*)  d_in[1];
    const int*   neigh_list  = (const int*)  d_in[2];
    const float* es1_w = (const float*)d_in[3];
    const float* es1_b = (const float*)d_in[4];
    const float* es2_w = (const float*)d_in[5];
    const float* es2_b = (const float*)d_in[6];
    const float* fs1_w = (const float*)d_in[7];
    const float* fs1_b = (const float*)d_in[8];
    const float* fs2_w = (const float*)d_in[9];
    const float* fs2_b = (const float*)d_in[10];
    const float* en1_w = (const float*)d_in[11];
    const float* en1_b = (const float*)d_in[12];
    const float* en2_w = (const float*)d_in[13];
    const float* en2_b = (const float*)d_in[14];
    const float* en3_w = (const float*)d_in[15];
    const float* en3_b = (const float*)d_in[16];
    float* out = (float*)d_out;

    pack_kernel<<<(SN + 255) / 256, 256>>>(inputs, input_types,
                                           es1_w, es1_b, es2_w, es2_b,
                                           fs1_w, fs1_b, fs2_w, fs2_b, en1_w);

    descriptor_kernel<<<SN / 8, 256>>>(neigh_list,
                                       en1_b, en2_w, en2_b, en3_w, en3_b,
                                       out);
}